// round 11
// baseline (speedup 1.0000x reference)
#include <cuda_runtime.h>
#include <cuda_fp16.h>
#include <cstdint>

// Problem constants (fixed shapes)
#define N_NODES 50000
#define T_STEPS 12
#define F_IN    128
#define HEADS   4
#define DDIM    128
#define E_EDGES 800000
#define NEG_SLOPE 0.2f
#define D3      384

#define ND (N_NODES * DDIM)
#define NH (N_NODES * HEADS)

// ---------------- scratch (device globals) ----------------
__device__ __half d_Wg16[DDIM * F_IN];     // [n][k]
__device__ __half d_Wih16[D3 * DDIM];      // [n][k] (native row-major)
__device__ __half d_Whh16[D3 * DDIM];
__device__ __half d_hf16[ND];              // GAT h features (edge gather only)
__device__ float  d_alS[NH];
__device__ float  d_alD[NH];
__device__ float  d_denom[NH];
__device__ float  d_acc[ND];
__device__ __half d_g16[ND];
__device__ __half d_r16[ND];               // sigmoid(i_r+h_r), fp16
__device__ __half d_z16[ND];               // sigmoid(i_z+h_z), fp16
__device__ float  d_pn[ND];                // i_n + bih_n
__device__ float  d_qn[ND];                // h_n + bhh_n
__device__ float  d_hstate[ND];            // exact fp32 GRU state
__device__ __half d_h16[ND];               // fp16 copy (GEMM input)

#define ROWH 136                            // halves per smem row (pad)
#define TILEH (128 * ROWH)                  // halves per 128-row tile
#define ATT_SMEM_BYTES  (2 * TILEH * 2 + 2 * 512 * 4)
// pair kernel: 2 A tiles (64 rows) + 2 W tiles (128 rows)
#define PAIR_SMEM_BYTES ((2 * 64 * ROWH + 2 * 128 * ROWH) * 2)

__device__ __forceinline__ void mma16816(float* c, const uint32_t* a, const uint32_t* b) {
    asm volatile(
        "mma.sync.aligned.m16n8k16.row.col.f32.f16.f16.f32 "
        "{%0,%1,%2,%3}, {%4,%5,%6,%7}, {%8,%9}, {%0,%1,%2,%3};\n"
        : "+f"(c[0]), "+f"(c[1]), "+f"(c[2]), "+f"(c[3])
        : "r"(a[0]), "r"(a[1]), "r"(a[2]), "r"(a[3]), "r"(b[0]), "r"(b[1]));
}

__device__ __forceinline__ void cp_async16(uint32_t saddr, const void* gptr, int srcsize) {
    asm volatile("cp.async.cg.shared.global [%0], [%1], 16, %2;"
                 :: "r"(saddr), "l"(gptr), "r"(srcsize));
}

__device__ __forceinline__ float tanh_fast(float x) {
    float r;
    asm("tanh.approx.f32 %0, %1;" : "=f"(r) : "f"(x));
    return r;
}

// ---------------- utility kernels ----------------
__global__ void zero_kernel(float* p, __half* q, int n) {
    int i = blockIdx.x * blockDim.x + threadIdx.x;
    if (i < n) { p[i] = 0.0f; q[i] = __float2half(0.0f); }
}

__global__ void conv_w_nk(const float* __restrict__ W, __half* __restrict__ W16, int n) {
    int i = blockIdx.x * blockDim.x + threadIdx.x;
    if (i < n) W16[i] = __float2half_rn(W[i]);
}

// Wg [k][n] row-major -> Wg16 [n][k]
__global__ void conv_wg(const float* __restrict__ Wg, __half* __restrict__ Wg16) {
    int i = blockIdx.x * blockDim.x + threadIdx.x;
    if (i < DDIM * F_IN) {
        int n = i >> 7, k = i & 127;
        Wg16[i] = __float2half_rn(Wg[k * DDIM + n]);
    }
}

// ---------------- fp16 GEMM + fused attention-logit epilogue ----------------
__global__ __launch_bounds__(256, 2) void gemm_att(
    const float* __restrict__ A, int lda, int M,
    const __half* __restrict__ Wt,
    __half* __restrict__ hf16,
    const float* __restrict__ a_src, const float* __restrict__ a_dst,
    float* __restrict__ alS, float* __restrict__ alD,
    float* __restrict__ denom, float* __restrict__ acc)
{
    extern __shared__ __half smh[];
    __half* As = smh;                 // [128][ROWH]
    __half* Ws = smh + TILEH;         // [128][ROWH]
    float* sS = (float*)(smh + 2 * TILEH);   // [512]
    float* sD = sS + 512;

    const int tid  = threadIdx.x;
    const int lane = tid & 31;
    const int wid  = tid >> 5;
    const int wm   = (wid & 3) * 32;
    const int wn   = (wid >> 2) * 64;
    const int row0 = blockIdx.x * 128;
    const int lq   = lane >> 2;
    const int lr   = lane & 3;

    if (tid < 256) { sS[tid] = 0.f; sS[tid + 256] = 0.f;
                     sD[tid] = 0.f; sD[tid + 256] = 0.f; }

    const uint32_t sW = (uint32_t)__cvta_generic_to_shared(Ws);
    {
        int ra = tid >> 4, c16 = tid & 15;
#pragma unroll
        for (int i = 0; i < 8; i++) {
            int r = ra + i * 16;
            cp_async16(sW + (uint32_t)((r * ROWH + c16 * 8) * 2),
                       &Wt[(long)r * 128 + c16 * 8], 16);
        }
        asm volatile("cp.async.commit_group;");
    }
    {
        int rb = tid >> 5, c4 = tid & 31;
#pragma unroll
        for (int i = 0; i < 16; i++) {
            int r = rb + i * 8;
            int gr = row0 + r;
            float4 v = make_float4(0.f, 0.f, 0.f, 0.f);
            if (gr < M) v = *(const float4*)&A[(long)gr * lda + c4 * 4];
            __half2 h0 = __floats2half2_rn(v.x, v.y);
            __half2 h1 = __floats2half2_rn(v.z, v.w);
            __half2* dp = (__half2*)&As[r * ROWH + c4 * 4];
            dp[0] = h0; dp[1] = h1;
        }
    }
    asm volatile("cp.async.wait_group 0;");
    __syncthreads();

    float cacc[2][8][4];
#pragma unroll
    for (int mf = 0; mf < 2; mf++)
#pragma unroll
        for (int nf = 0; nf < 8; nf++)
#pragma unroll
            for (int q = 0; q < 4; q++) cacc[mf][nf][q] = 0.0f;

#pragma unroll
    for (int ks = 0; ks < 8; ks++) {
        const int kh = ks * 16;
        uint32_t af[2][4];
#pragma unroll
        for (int mf = 0; mf < 2; mf++) {
            int rw = wm + mf * 16 + lq;
            af[mf][0] = *(const uint32_t*)&As[rw * ROWH + kh + 2 * lr];
            af[mf][1] = *(const uint32_t*)&As[(rw + 8) * ROWH + kh + 2 * lr];
            af[mf][2] = *(const uint32_t*)&As[rw * ROWH + kh + 8 + 2 * lr];
            af[mf][3] = *(const uint32_t*)&As[(rw + 8) * ROWH + kh + 8 + 2 * lr];
        }
#pragma unroll
        for (int nf = 0; nf < 8; nf++) {
            int cc = wn + nf * 8 + lq;
            uint32_t bf[2];
            bf[0] = *(const uint32_t*)&Ws[cc * ROWH + kh + 2 * lr];
            bf[1] = *(const uint32_t*)&Ws[cc * ROWH + kh + 8 + 2 * lr];
#pragma unroll
            for (int mf = 0; mf < 2; mf++)
                mma16816(cacc[mf][nf], af[mf], bf);
        }
    }

    // ===== fused attention epilogue =====
    __syncthreads();
    {
        float aSv[8][2], aDv[8][2];
#pragma unroll
        for (int nf = 0; nf < 8; nf++) {
            int cc = wn + nf * 8 + lr * 2;
            aSv[nf][0] = a_src[cc];     aSv[nf][1] = a_src[cc + 1];
            aDv[nf][0] = a_dst[cc];     aDv[nf][1] = a_dst[cc + 1];
        }
#pragma unroll
        for (int mf = 0; mf < 2; mf++) {
#pragma unroll
            for (int half = 0; half < 2; half++) {
                int lrow = wm + mf * 16 + lq + half * 8;
                int h0 = wn >> 5;
                float pS0 = 0.f, pD0 = 0.f, pS1 = 0.f, pD1 = 0.f;
#pragma unroll
                for (int nf = 0; nf < 4; nf++) {
                    float v0 = cacc[mf][nf][half * 2], v1 = cacc[mf][nf][half * 2 + 1];
                    pS0 += v0 * aSv[nf][0] + v1 * aSv[nf][1];
                    pD0 += v0 * aDv[nf][0] + v1 * aDv[nf][1];
                }
#pragma unroll
                for (int nf = 4; nf < 8; nf++) {
                    float v0 = cacc[mf][nf][half * 2], v1 = cacc[mf][nf][half * 2 + 1];
                    pS1 += v0 * aSv[nf][0] + v1 * aSv[nf][1];
                    pD1 += v0 * aDv[nf][0] + v1 * aDv[nf][1];
                }
                atomicAdd(&sS[lrow * HEADS + h0], pS0);
                atomicAdd(&sD[lrow * HEADS + h0], pD0);
                atomicAdd(&sS[lrow * HEADS + h0 + 1], pS1);
                atomicAdd(&sD[lrow * HEADS + h0 + 1], pD1);
            }
        }
    }
    __syncthreads();
    for (int i = tid; i < 128 * HEADS; i += 256) {
        int lrow = i >> 2;
        int gr = row0 + lrow;
        if (gr < M) {
            float sg = sS[i], dg = sD[i];
            float v = sg + dg;
            float e = v > 0.0f ? v : NEG_SLOPE * v;
            float w = __expf(e);
            alS[(long)gr * HEADS + (i & 3)] = sg;
            alD[(long)gr * HEADS + (i & 3)] = dg;
            denom[(long)gr * HEADS + (i & 3)] = w;
            sD[i] = w;
        }
    }
    __syncthreads();
#pragma unroll
    for (int mf = 0; mf < 2; mf++) {
        int lrow = wm + mf * 16 + lq;
#pragma unroll
        for (int nf = 0; nf < 8; nf++) {
            int cc = wn + nf * 8 + lr * 2;
            int head = cc >> 5;
            int r_b = row0 + lrow;
            if (r_b < M) {
                float w = sD[lrow * HEADS + head];
                float2 o = make_float2(cacc[mf][nf][0], cacc[mf][nf][1]);
                *(__half2*)&hf16[(long)r_b * DDIM + cc] = __floats2half2_rn(o.x, o.y);
                *(float2*)&acc[(long)r_b * DDIM + cc] = make_float2(o.x * w, o.y * w);
            }
            if (r_b + 8 < M) {
                float w = sD[(lrow + 8) * HEADS + head];
                float2 o = make_float2(cacc[mf][nf][2], cacc[mf][nf][3]);
                *(__half2*)&hf16[(long)(r_b + 8) * DDIM + cc] = __floats2half2_rn(o.x, o.y);
                *(float2*)&acc[(long)(r_b + 8) * DDIM + cc] = make_float2(o.x * w, o.y * w);
            }
        }
    }
}

// ---------------- paired gate GEMM ----------------
// grid (782, 3): 64-row tile, chunk = blockIdx.y (0=r,1=z,2=n).
// Computes i_c = g16 @ Wih_c^T and h_c = h16 @ Whh_c^T together.
// r,z: writes sigmoid(i+h+biases) fp16. n: writes i_n+bih, h_n+bhh fp32.
__global__ __launch_bounds__(256, 2) void gemm_pair(
    const __half* __restrict__ Ag, const __half* __restrict__ Ah, int M,
    const __half* __restrict__ Wih, const __half* __restrict__ Whh,
    const float* __restrict__ bih, const float* __restrict__ bhh,
    __half* __restrict__ r16, __half* __restrict__ z16,
    float* __restrict__ pn, float* __restrict__ qn)
{
    extern __shared__ __half smh[];
    __half* Ags = smh;                         // [64][ROWH]
    __half* Ahs = smh + 64 * ROWH;             // [64][ROWH]
    __half* Wis = smh + 128 * ROWH;            // [128][ROWH]
    __half* Whs = smh + 128 * ROWH + TILEH;    // [128][ROWH]

    const int chunk = blockIdx.y;
    const int c0    = chunk * 128;
    const int tid   = threadIdx.x;
    const int lane  = tid & 31;
    const int wid   = tid >> 5;
    const int wm    = (wid & 1) * 32;     // 2 row groups
    const int wn    = (wid >> 1) * 32;    // 4 col groups
    const int row0  = blockIdx.x * 64;
    const int lq    = lane >> 2;
    const int lr    = lane & 3;

    const uint32_t sAg = (uint32_t)__cvta_generic_to_shared(Ags);
    const uint32_t sAh = (uint32_t)__cvta_generic_to_shared(Ahs);
    const uint32_t sWi = (uint32_t)__cvta_generic_to_shared(Wis);
    const uint32_t sWh = (uint32_t)__cvta_generic_to_shared(Whs);

    {   // A tiles: 64 rows x 16 8-half chunks = 1024 slots each, 4/thread
        int ra = tid >> 4, c16 = tid & 15;
#pragma unroll
        for (int i = 0; i < 4; i++) {
            int r = ra + i * 16;
            int gr = row0 + r;
            long off = (long)(gr < M ? gr : 0) * 128 + c16 * 8;
            int sz = gr < M ? 16 : 0;
            cp_async16(sAg + (uint32_t)((r * ROWH + c16 * 8) * 2), &Ag[off], sz);
            cp_async16(sAh + (uint32_t)((r * ROWH + c16 * 8) * 2), &Ah[off], sz);
        }
        // W tiles: 128 rows x 16 = 2048 slots each, 8/thread
#pragma unroll
        for (int i = 0; i < 8; i++) {
            int slot = tid + i * 256;
            int r = slot >> 4, c16w = slot & 15;
            long off = (long)(c0 + r) * 128 + c16w * 8;
            cp_async16(sWi + (uint32_t)((r * ROWH + c16w * 8) * 2), &Wih[off], 16);
            cp_async16(sWh + (uint32_t)((r * ROWH + c16w * 8) * 2), &Whh[off], 16);
        }
        asm volatile("cp.async.commit_group;");
        asm volatile("cp.async.wait_group 0;");
    }
    __syncthreads();

    float ci[2][4][4], ch[2][4][4];
#pragma unroll
    for (int mf = 0; mf < 2; mf++)
#pragma unroll
        for (int nf = 0; nf < 4; nf++)
#pragma unroll
            for (int q = 0; q < 4; q++) { ci[mf][nf][q] = 0.0f; ch[mf][nf][q] = 0.0f; }

#pragma unroll
    for (int ks = 0; ks < 8; ks++) {
        const int kh = ks * 16;
        uint32_t ag[2][4], ah[2][4];
#pragma unroll
        for (int mf = 0; mf < 2; mf++) {
            int rw = wm + mf * 16 + lq;
            ag[mf][0] = *(const uint32_t*)&Ags[rw * ROWH + kh + 2 * lr];
            ag[mf][1] = *(const uint32_t*)&Ags[(rw + 8) * ROWH + kh + 2 * lr];
            ag[mf][2] = *(const uint32_t*)&Ags[rw * ROWH + kh + 8 + 2 * lr];
            ag[mf][3] = *(const uint32_t*)&Ags[(rw + 8) * ROWH + kh + 8 + 2 * lr];
            ah[mf][0] = *(const uint32_t*)&Ahs[rw * ROWH + kh + 2 * lr];
            ah[mf][1] = *(const uint32_t*)&Ahs[(rw + 8) * ROWH + kh + 2 * lr];
            ah[mf][2] = *(const uint32_t*)&Ahs[rw * ROWH + kh + 8 + 2 * lr];
            ah[mf][3] = *(const uint32_t*)&Ahs[(rw + 8) * ROWH + kh + 8 + 2 * lr];
        }
#pragma unroll
        for (int nf = 0; nf < 4; nf++) {
            int cc = wn + nf * 8 + lq;
            uint32_t bi[2], bh[2];
            bi[0] = *(const uint32_t*)&Wis[cc * ROWH + kh + 2 * lr];
            bi[1] = *(const uint32_t*)&Wis[cc * ROWH + kh + 8 + 2 * lr];
            bh[0] = *(const uint32_t*)&Whs[cc * ROWH + kh + 2 * lr];
            bh[1] = *(const uint32_t*)&Whs[cc * ROWH + kh + 8 + 2 * lr];
#pragma unroll
            for (int mf = 0; mf < 2; mf++) {
                mma16816(ci[mf][nf], ag[mf], bi);
                mma16816(ch[mf][nf], ah[mf], bh);
            }
        }
    }

    // epilogue
#pragma unroll
    for (int mf = 0; mf < 2; mf++) {
#pragma unroll
        for (int half = 0; half < 2; half++) {
            int row = row0 + wm + mf * 16 + lq + half * 8;
            if (row >= M) continue;
#pragma unroll
            for (int nf = 0; nf < 4; nf++) {
                int cc = wn + nf * 8 + lr * 2;
                float bi0 = bih[c0 + cc], bi1 = bih[c0 + cc + 1];
                float bh0 = bhh[c0 + cc], bh1 = bhh[c0 + cc + 1];
                float i0 = ci[mf][nf][half * 2]     + bi0;
                float i1 = ci[mf][nf][half * 2 + 1] + bi1;
                float h0 = ch[mf][nf][half * 2]     + bh0;
                float h1 = ch[mf][nf][half * 2 + 1] + bh1;
                long base = (long)row * DDIM + cc;
                if (chunk < 2) {
                    float s0 = 1.0f / (1.0f + __expf(-(i0 + h0)));
                    float s1 = 1.0f / (1.0f + __expf(-(i1 + h1)));
                    __half* dst = chunk ? z16 : r16;
                    *(__half2*)&dst[base] = __floats2half2_rn(s0, s1);
                } else {
                    *(float2*)&pn[base] = make_float2(i0, i1);
                    *(float2*)&qn[base] = make_float2(h0, h1);
                }
            }
        }
    }
}

// ---------------- edge pass (fp16 gather, fp32 RED) ----------------
__device__ __forceinline__ void red_add_v4(float* addr, float a, float b, float c, float d) {
    asm volatile("red.global.add.v4.f32 [%0], {%1,%2,%3,%4};"
                 :: "l"(addr), "f"(a), "f"(b), "f"(c), "f"(d) : "memory");
}

__global__ __launch_bounds__(256) void edge_kernel(
    const int* __restrict__ src_arr, const int* __restrict__ dst_arr,
    const float* __restrict__ alS, const float* __restrict__ alD,
    const __half* __restrict__ hf16,
    float* __restrict__ denom, float* __restrict__ acc)
{
    long gw = (long)blockIdx.x * (blockDim.x >> 5) + (threadIdx.x >> 5);
    if (gw >= E_EDGES) return;
    int lane = threadIdx.x & 31;
    int head = lane >> 3;

    int s = src_arr[gw];
    int d = dst_arr[gw];

    float v = alS[s * HEADS + head] + alD[d * HEADS + head];
    float e = v > 0.0f ? v : NEG_SLOPE * v;
    float w = __expf(e);

    if ((lane & 7) == 0) atomicAdd(&denom[d * HEADS + head], w);

    uint2 hv = ((const uint2*)hf16)[s * 32 + lane];
    float2 f0 = __half22float2(*(__half2*)&hv.x);
    float2 f1 = __half22float2(*(__half2*)&hv.y);
    red_add_v4(&acc[d * DDIM + lane * 4], w * f0.x, w * f0.y, w * f1.x, w * f1.y);
}

// ---------------- finalize GAT: g16 = fp16(relu(acc/denom + bg)) ----------------
__global__ void finalize_gat(
    const float* __restrict__ acc, const float* __restrict__ denom,
    const float* __restrict__ bg, __half* __restrict__ g16)
{
    int idx = blockIdx.x * blockDim.x + threadIdx.x;   // over N*32 float4s
    if (idx >= N_NODES * 32) return;
    int n = idx >> 5;
    int c4 = idx & 31;
    int head = c4 >> 3;
    float inv = 1.0f / (denom[n * HEADS + head] + 1e-16f);
    float4 a = ((const float4*)acc)[idx];
    float4 b = ((const float4*)bg)[c4];
    __half2 p0 = __floats2half2_rn(fmaxf(a.x * inv + b.x, 0.0f),
                                   fmaxf(a.y * inv + b.y, 0.0f));
    __half2 p1 = __floats2half2_rn(fmaxf(a.z * inv + b.z, 0.0f),
                                   fmaxf(a.w * inv + b.w, 0.0f));
    ((__half2*)g16)[idx * 2] = p0;
    ((__half2*)g16)[idx * 2 + 1] = p1;
}

// ---------------- GRU gates v2: h = (1-z)*tanh(p + r*q) + z*h ----------------
__global__ void gru_gates2(
    const __half* __restrict__ r16, const __half* __restrict__ z16,
    const float* __restrict__ pn, const float* __restrict__ qn,
    float* __restrict__ h, __half* __restrict__ h16)
{
    int idx = blockIdx.x * blockDim.x + threadIdx.x;   // over N*32 float4s
    if (idx >= N_NODES * 32) return;
    uint2 rv = ((const uint2*)r16)[idx];
    uint2 zv = ((const uint2*)z16)[idx];
    float2 r0 = __half22float2(*(__half2*)&rv.x);
    float2 r1 = __half22float2(*(__half2*)&rv.y);
    float2 z0 = __half22float2(*(__half2*)&zv.x);
    float2 z1 = __half22float2(*(__half2*)&zv.y);
    float4 p = ((const float4*)pn)[idx];
    float4 q = ((const float4*)qn)[idx];
    float4 hv = ((const float4*)h)[idx];
    float rr[4] = {r0.x, r0.y, r1.x, r1.y};
    float zz[4] = {z0.x, z0.y, z1.x, z1.y};
    float4 ho;
#pragma unroll
    for (int k = 0; k < 4; k++) {
        float nn = tanh_fast((&p.x)[k] + rr[k] * (&q.x)[k]);
        (&ho.x)[k] = (1.0f - zz[k]) * nn + zz[k] * (&hv.x)[k];
    }
    ((float4*)h)[idx] = ho;
    ((__half2*)h16)[idx * 2]     = __floats2half2_rn(ho.x, ho.y);
    ((__half2*)h16)[idx * 2 + 1] = __floats2half2_rn(ho.z, ho.w);
}

// ---------------- final linear ----------------
__global__ __launch_bounds__(256) void final_linear(
    const float* __restrict__ h, const float* __restrict__ Wl,
    const float* __restrict__ bl, float* __restrict__ out)
{
    int warp = (blockIdx.x * blockDim.x + threadIdx.x) >> 5;
    int lane = threadIdx.x & 31;
    if (warp >= N_NODES) return;
    float4 hv = ((const float4*)h)[warp * 32 + lane];
    float4 wv = ((const float4*)Wl)[lane];
    float s = hv.x * wv.x + hv.y * wv.y + hv.z * wv.z + hv.w * wv.w;
#pragma unroll
    for (int off = 16; off > 0; off >>= 1)
        s += __shfl_down_sync(0xffffffffu, s, off);
    if (lane == 0) out[warp] = s + bl[0];
}

// ---------------- launcher ----------------
extern "C" void kernel_launch(void* const* d_in, const int* in_sizes, int n_in,
                              void* d_out, int out_size)
{
    const float* x   = (const float*)d_in[0];
    const int*   ei  = (const int*)d_in[1];
    const float* Wg  = (const float*)d_in[2];
    const float* as  = (const float*)d_in[3];
    const float* ad  = (const float*)d_in[4];
    const float* bg  = (const float*)d_in[5];
    const float* Wih = (const float*)d_in[6];
    const float* Whh = (const float*)d_in[7];
    const float* bih = (const float*)d_in[8];
    const float* bhh = (const float*)d_in[9];
    const float* Wl  = (const float*)d_in[10];
    const float* bl  = (const float*)d_in[11];
    float* out = (float*)d_out;

    float *alS, *alD, *denom, *acc, *pn, *qn, *hstate;
    __half *Wg16, *Wih16, *Whh16, *hf16, *g16, *r16, *z16, *h16;
    cudaGetSymbolAddress((void**)&alS,    d_alS);
    cudaGetSymbolAddress((void**)&alD,    d_alD);
    cudaGetSymbolAddress((void**)&denom,  d_denom);
    cudaGetSymbolAddress((void**)&acc,    d_acc);
    cudaGetSymbolAddress((void**)&pn,     d_pn);
    cudaGetSymbolAddress((void**)&qn,     d_qn);
    cudaGetSymbolAddress((void**)&hstate, d_hstate);
    cudaGetSymbolAddress((void**)&Wg16,   d_Wg16);
    cudaGetSymbolAddress((void**)&Wih16,  d_Wih16);
    cudaGetSymbolAddress((void**)&Whh16,  d_Whh16);
    cudaGetSymbolAddress((void**)&hf16,   d_hf16);
    cudaGetSymbolAddress((void**)&g16,    d_g16);
    cudaGetSymbolAddress((void**)&r16,    d_r16);
    cudaGetSymbolAddress((void**)&z16,    d_z16);
    cudaGetSymbolAddress((void**)&h16,    d_h16);

    cudaFuncSetAttribute(gemm_att,
                         cudaFuncAttributeMaxDynamicSharedMemorySize, ATT_SMEM_BYTES);
    cudaFuncSetAttribute(gemm_pair,
                         cudaFuncAttributeMaxDynamicSharedMemorySize, PAIR_SMEM_BYTES);

    const int GX = (N_NODES + 127) / 128;   // 391
    const int GP = (N_NODES + 63) / 64;     // 782

    // prologue: zero state, convert weights to fp16
    zero_kernel<<<(ND + 255) / 256, 256>>>(hstate, h16, ND);
    conv_wg<<<(DDIM * F_IN + 255) / 256, 256>>>(Wg, Wg16);
    conv_w_nk<<<(D3 * DDIM + 255) / 256, 256>>>(Wih, Wih16, D3 * DDIM);
    conv_w_nk<<<(D3 * DDIM + 255) / 256, 256>>>(Whh, Whh16, D3 * DDIM);

    for (int t = 0; t < T_STEPS; t++) {
        // 1) h = x_t @ W_gat (+ fused attention logits + self-loop init)
        gemm_att<<<GX, 256, ATT_SMEM_BYTES>>>(
            x + (long)t * F_IN, T_STEPS * F_IN, N_NODES, Wg16, hf16,
            as, ad, alS, alD, denom, acc);

        // 2) edge pass (fp16 gather, fp32 RED accumulate)
        const int* src = ei + (long)t * 2 * E_EDGES;
        const int* dst = src + E_EDGES;
        edge_kernel<<<(E_EDGES * 32 + 255) / 256, 256>>>(src, dst, alS, alD, hf16, denom, acc);

        // 3) g16 = fp16(relu(acc/denom + b_gat))
        finalize_gat<<<(N_NODES * 32 + 255) / 256, 256>>>(acc, denom, bg, g16);

        // 4) paired gate GEMMs: r16/z16 (post-sigmoid fp16), pn/qn (fp32)
        gemm_pair<<<dim3(GP, 3), 256, PAIR_SMEM_BYTES>>>(
            g16, h16, N_NODES, Wih16, Whh16, bih, bhh, r16, z16, pn, qn);

        // 5) GRU update (writes exact h + fp16 copy)
        gru_gates2<<<(N_NODES * 32 + 255) / 256, 256>>>(r16, z16, pn, qn, hstate, h16);
    }

    final_linear<<<(N_NODES * 32 + 255) / 256, 256>>>(hstate, Wl, bl, out);
}

// round 12
// speedup vs baseline: 1.1025x; 1.1025x over previous
#include <cuda_runtime.h>
#include <cuda_fp16.h>
#include <cstdint>

// Problem constants (fixed shapes)
#define N_NODES 50000
#define T_STEPS 12
#define F_IN    128
#define HEADS   4
#define DDIM    128
#define E_EDGES 800000
#define NEG_SLOPE 0.2f
#define D3      384

#define ND (N_NODES * DDIM)
#define NH (N_NODES * HEADS)

// ---------------- scratch (device globals) ----------------
__device__ __half d_Wg16[DDIM * F_IN];     // [n][k]
__device__ __half d_Wih16[D3 * DDIM];      // [n][k] (native row-major)
__device__ __half d_Whh16[D3 * DDIM];
// per-timestep GAT outputs (hoisted out of the recurrence)
__device__ __half d_hf16[T_STEPS][ND];     // fp16 h features (edge gather)
__device__ float  d_alS[T_STEPS][NH];
__device__ float  d_alD[T_STEPS][NH];
__device__ float  d_denom[T_STEPS][NH];
__device__ float  d_acc[T_STEPS][ND];
// recurrence scratch
__device__ __half d_g16[ND];
__device__ __half d_gi16[N_NODES * D3];
__device__ __half d_gh16[N_NODES * D3];
__device__ float  d_hstate[ND];            // exact fp32 GRU state
__device__ __half d_h16[ND];               // fp16 copy (GEMM input)

#define ROWH 136                            // halves per smem row (pad)
#define TILEH (128 * ROWH)                  // halves per 128-row tile
#define GEMM_SMEM_BYTES (2 * TILEH * 2)
#define ATT_SMEM_BYTES  (2 * TILEH * 2 + 2 * 512 * 4)

__device__ __forceinline__ void mma16816(float* c, const uint32_t* a, const uint32_t* b) {
    asm volatile(
        "mma.sync.aligned.m16n8k16.row.col.f32.f16.f16.f32 "
        "{%0,%1,%2,%3}, {%4,%5,%6,%7}, {%8,%9}, {%0,%1,%2,%3};\n"
        : "+f"(c[0]), "+f"(c[1]), "+f"(c[2]), "+f"(c[3])
        : "r"(a[0]), "r"(a[1]), "r"(a[2]), "r"(a[3]), "r"(b[0]), "r"(b[1]));
}

__device__ __forceinline__ void cp_async16(uint32_t saddr, const void* gptr, int srcsize) {
    asm volatile("cp.async.cg.shared.global [%0], [%1], 16, %2;"
                 :: "r"(saddr), "l"(gptr), "r"(srcsize));
}

__device__ __forceinline__ float tanh_fast(float x) {
    float r;
    asm("tanh.approx.f32 %0, %1;" : "=f"(r) : "f"(x));
    return r;
}

// ---------------- utility kernels ----------------
__global__ void zero_kernel(float* p, __half* q, int n) {
    int i = blockIdx.x * blockDim.x + threadIdx.x;
    if (i < n) { p[i] = 0.0f; q[i] = __float2half(0.0f); }
}

__global__ void conv_w_nk(const float* __restrict__ W, __half* __restrict__ W16, int n) {
    int i = blockIdx.x * blockDim.x + threadIdx.x;
    if (i < n) W16[i] = __float2half_rn(W[i]);
}

// Wg [k][n] row-major -> Wg16 [n][k]
__global__ void conv_wg(const float* __restrict__ Wg, __half* __restrict__ Wg16) {
    int i = blockIdx.x * blockDim.x + threadIdx.x;
    if (i < DDIM * F_IN) {
        int n = i >> 7, k = i & 127;
        Wg16[i] = __float2half_rn(Wg[k * DDIM + n]);
    }
}

// ---------------- batched fp16 GEMM + fused attention epilogue ----------------
// grid (391, T_STEPS): blockIdx.y = timestep. A = x + t*F_IN, lda = T*F_IN.
__global__ __launch_bounds__(256, 2) void gemm_att(
    const float* __restrict__ X, int M,
    const __half* __restrict__ Wt,
    __half* __restrict__ hf16_all,
    const float* __restrict__ a_src, const float* __restrict__ a_dst,
    float* __restrict__ alS_all, float* __restrict__ alD_all,
    float* __restrict__ denom_all, float* __restrict__ acc_all)
{
    extern __shared__ __half smh[];
    __half* As = smh;                 // [128][ROWH]
    __half* Ws = smh + TILEH;         // [128][ROWH]
    float* sS = (float*)(smh + 2 * TILEH);   // [512]
    float* sD = sS + 512;

    const int t = blockIdx.y;
    const float* A = X + (long)t * F_IN;
    const int lda = T_STEPS * F_IN;
    __half* hf16 = hf16_all + (long)t * ND;
    float* alS   = alS_all + (long)t * NH;
    float* alD   = alD_all + (long)t * NH;
    float* denom = denom_all + (long)t * NH;
    float* acc   = acc_all + (long)t * ND;

    const int tid  = threadIdx.x;
    const int lane = tid & 31;
    const int wid  = tid >> 5;
    const int wm   = (wid & 3) * 32;
    const int wn   = (wid >> 2) * 64;
    const int row0 = blockIdx.x * 128;
    const int lq   = lane >> 2;
    const int lr   = lane & 3;

    if (tid < 256) { sS[tid] = 0.f; sS[tid + 256] = 0.f;
                     sD[tid] = 0.f; sD[tid + 256] = 0.f; }

    const uint32_t sW = (uint32_t)__cvta_generic_to_shared(Ws);
    {
        int ra = tid >> 4, c16 = tid & 15;
#pragma unroll
        for (int i = 0; i < 8; i++) {
            int r = ra + i * 16;
            cp_async16(sW + (uint32_t)((r * ROWH + c16 * 8) * 2),
                       &Wt[(long)r * 128 + c16 * 8], 16);
        }
        asm volatile("cp.async.commit_group;");
    }
    {
        int rb = tid >> 5, c4 = tid & 31;
#pragma unroll
        for (int i = 0; i < 16; i++) {
            int r = rb + i * 8;
            int gr = row0 + r;
            float4 v = make_float4(0.f, 0.f, 0.f, 0.f);
            if (gr < M) v = *(const float4*)&A[(long)gr * lda + c4 * 4];
            __half2 h0 = __floats2half2_rn(v.x, v.y);
            __half2 h1 = __floats2half2_rn(v.z, v.w);
            __half2* dp = (__half2*)&As[r * ROWH + c4 * 4];
            dp[0] = h0; dp[1] = h1;
        }
    }
    asm volatile("cp.async.wait_group 0;");
    __syncthreads();

    float cacc[2][8][4];
#pragma unroll
    for (int mf = 0; mf < 2; mf++)
#pragma unroll
        for (int nf = 0; nf < 8; nf++)
#pragma unroll
            for (int q = 0; q < 4; q++) cacc[mf][nf][q] = 0.0f;

#pragma unroll
    for (int ks = 0; ks < 8; ks++) {
        const int kh = ks * 16;
        uint32_t af[2][4];
#pragma unroll
        for (int mf = 0; mf < 2; mf++) {
            int rw = wm + mf * 16 + lq;
            af[mf][0] = *(const uint32_t*)&As[rw * ROWH + kh + 2 * lr];
            af[mf][1] = *(const uint32_t*)&As[(rw + 8) * ROWH + kh + 2 * lr];
            af[mf][2] = *(const uint32_t*)&As[rw * ROWH + kh + 8 + 2 * lr];
            af[mf][3] = *(const uint32_t*)&As[(rw + 8) * ROWH + kh + 8 + 2 * lr];
        }
#pragma unroll
        for (int nf = 0; nf < 8; nf++) {
            int cc = wn + nf * 8 + lq;
            uint32_t bf[2];
            bf[0] = *(const uint32_t*)&Ws[cc * ROWH + kh + 2 * lr];
            bf[1] = *(const uint32_t*)&Ws[cc * ROWH + kh + 8 + 2 * lr];
#pragma unroll
            for (int mf = 0; mf < 2; mf++)
                mma16816(cacc[mf][nf], af[mf], bf);
        }
    }

    // ===== fused attention epilogue =====
    __syncthreads();
    {
        float aSv[8][2], aDv[8][2];
#pragma unroll
        for (int nf = 0; nf < 8; nf++) {
            int cc = wn + nf * 8 + lr * 2;
            aSv[nf][0] = a_src[cc];     aSv[nf][1] = a_src[cc + 1];
            aDv[nf][0] = a_dst[cc];     aDv[nf][1] = a_dst[cc + 1];
        }
#pragma unroll
        for (int mf = 0; mf < 2; mf++) {
#pragma unroll
            for (int half = 0; half < 2; half++) {
                int lrow = wm + mf * 16 + lq + half * 8;
                int h0 = wn >> 5;
                float pS0 = 0.f, pD0 = 0.f, pS1 = 0.f, pD1 = 0.f;
#pragma unroll
                for (int nf = 0; nf < 4; nf++) {
                    float v0 = cacc[mf][nf][half * 2], v1 = cacc[mf][nf][half * 2 + 1];
                    pS0 += v0 * aSv[nf][0] + v1 * aSv[nf][1];
                    pD0 += v0 * aDv[nf][0] + v1 * aDv[nf][1];
                }
#pragma unroll
                for (int nf = 4; nf < 8; nf++) {
                    float v0 = cacc[mf][nf][half * 2], v1 = cacc[mf][nf][half * 2 + 1];
                    pS1 += v0 * aSv[nf][0] + v1 * aSv[nf][1];
                    pD1 += v0 * aDv[nf][0] + v1 * aDv[nf][1];
                }
                atomicAdd(&sS[lrow * HEADS + h0], pS0);
                atomicAdd(&sD[lrow * HEADS + h0], pD0);
                atomicAdd(&sS[lrow * HEADS + h0 + 1], pS1);
                atomicAdd(&sD[lrow * HEADS + h0 + 1], pD1);
            }
        }
    }
    __syncthreads();
    for (int i = tid; i < 128 * HEADS; i += 256) {
        int lrow = i >> 2;
        int gr = row0 + lrow;
        if (gr < M) {
            float sg = sS[i], dg = sD[i];
            float v = sg + dg;
            float e = v > 0.0f ? v : NEG_SLOPE * v;
            float w = __expf(e);
            alS[(long)gr * HEADS + (i & 3)] = sg;
            alD[(long)gr * HEADS + (i & 3)] = dg;
            denom[(long)gr * HEADS + (i & 3)] = w;
            sD[i] = w;
        }
    }
    __syncthreads();
#pragma unroll
    for (int mf = 0; mf < 2; mf++) {
        int lrow = wm + mf * 16 + lq;
#pragma unroll
        for (int nf = 0; nf < 8; nf++) {
            int cc = wn + nf * 8 + lr * 2;
            int head = cc >> 5;
            int r_b = row0 + lrow;
            if (r_b < M) {
                float w = sD[lrow * HEADS + head];
                float2 o = make_float2(cacc[mf][nf][0], cacc[mf][nf][1]);
                *(__half2*)&hf16[(long)r_b * DDIM + cc] = __floats2half2_rn(o.x, o.y);
                *(float2*)&acc[(long)r_b * DDIM + cc] = make_float2(o.x * w, o.y * w);
            }
            if (r_b + 8 < M) {
                float w = sD[(lrow + 8) * HEADS + head];
                float2 o = make_float2(cacc[mf][nf][2], cacc[mf][nf][3]);
                *(__half2*)&hf16[(long)(r_b + 8) * DDIM + cc] = __floats2half2_rn(o.x, o.y);
                *(float2*)&acc[(long)(r_b + 8) * DDIM + cc] = make_float2(o.x * w, o.y * w);
            }
        }
    }
}

// ---------------- dual fp16 GEMM -> fp16 outputs ----------------
// grid (GX, 6): y/3 selects (gi|gh), y%3 selects 128-col gate chunk.
__global__ __launch_bounds__(256, 2) void gemm_f16_dual(
    const __half* __restrict__ Ag, const __half* __restrict__ Ah, int M,
    const __half* __restrict__ Wih, const __half* __restrict__ Whh,
    const float* __restrict__ bih, const float* __restrict__ bhh,
    __half* __restrict__ Cgi, __half* __restrict__ Cgh)
{
    extern __shared__ __half smh[];
    __half* As = smh;
    __half* Ws = smh + TILEH;

    const int which = blockIdx.y / 3;
    const int c0    = (blockIdx.y % 3) * 128;
    const __half* A  = which ? Ah : Ag;
    const __half* Wt = which ? Whh : Wih;
    const float* bias = which ? bhh : bih;
    __half* C = which ? Cgh : Cgi;

    const int tid  = threadIdx.x;
    const int lane = tid & 31;
    const int wid  = tid >> 5;
    const int wm   = (wid & 3) * 32;
    const int wn   = (wid >> 2) * 64;
    const int row0 = blockIdx.x * 128;
    const int lq   = lane >> 2;
    const int lr   = lane & 3;

    const uint32_t sA = (uint32_t)__cvta_generic_to_shared(As);
    const uint32_t sW = (uint32_t)__cvta_generic_to_shared(Ws);
    {
        int ra = tid >> 4, c16 = tid & 15;
#pragma unroll
        for (int i = 0; i < 8; i++) {
            int r = ra + i * 16;
            int gr = row0 + r;
            const __half* gp = &A[(long)(gr < M ? gr : 0) * 128 + c16 * 8];
            cp_async16(sA + (uint32_t)((r * ROWH + c16 * 8) * 2), gp, gr < M ? 16 : 0);
        }
#pragma unroll
        for (int i = 0; i < 8; i++) {
            int r = ra + i * 16;
            cp_async16(sW + (uint32_t)((r * ROWH + c16 * 8) * 2),
                       &Wt[(long)(c0 + r) * 128 + c16 * 8], 16);
        }
        asm volatile("cp.async.commit_group;");
        asm volatile("cp.async.wait_group 0;");
    }
    __syncthreads();

    float cacc[2][8][4];
#pragma unroll
    for (int mf = 0; mf < 2; mf++)
#pragma unroll
        for (int nf = 0; nf < 8; nf++)
#pragma unroll
            for (int q = 0; q < 4; q++) cacc[mf][nf][q] = 0.0f;

#pragma unroll
    for (int ks = 0; ks < 8; ks++) {
        const int kh = ks * 16;
        uint32_t af[2][4];
#pragma unroll
        for (int mf = 0; mf < 2; mf++) {
            int rw = wm + mf * 16 + lq;
            af[mf][0] = *(const uint32_t*)&As[rw * ROWH + kh + 2 * lr];
            af[mf][1] = *(const uint32_t*)&As[(rw + 8) * ROWH + kh + 2 * lr];
            af[mf][2] = *(const uint32_t*)&As[rw * ROWH + kh + 8 + 2 * lr];
            af[mf][3] = *(const uint32_t*)&As[(rw + 8) * ROWH + kh + 8 + 2 * lr];
        }
#pragma unroll
        for (int nf = 0; nf < 8; nf++) {
            int cc = wn + nf * 8 + lq;
            uint32_t bf[2];
            bf[0] = *(const uint32_t*)&Ws[cc * ROWH + kh + 2 * lr];
            bf[1] = *(const uint32_t*)&Ws[cc * ROWH + kh + 8 + 2 * lr];
#pragma unroll
            for (int mf = 0; mf < 2; mf++)
                mma16816(cacc[mf][nf], af[mf], bf);
        }
    }

#pragma unroll
    for (int mf = 0; mf < 2; mf++) {
        int r_b = row0 + wm + mf * 16 + lq;
#pragma unroll
        for (int nf = 0; nf < 8; nf++) {
            int cc = c0 + wn + nf * 8 + lr * 2;
            float b0 = bias[cc];
            float b1 = bias[cc + 1];
            if (r_b < M)
                *(__half2*)&C[(long)r_b * D3 + cc] =
                    __floats2half2_rn(cacc[mf][nf][0] + b0, cacc[mf][nf][1] + b1);
            if (r_b + 8 < M)
                *(__half2*)&C[(long)(r_b + 8) * D3 + cc] =
                    __floats2half2_rn(cacc[mf][nf][2] + b0, cacc[mf][nf][3] + b1);
        }
    }
}

// ---------------- edge pass (fp16 gather, fp32 RED) ----------------
__device__ __forceinline__ void red_add_v4(float* addr, float a, float b, float c, float d) {
    asm volatile("red.global.add.v4.f32 [%0], {%1,%2,%3,%4};"
                 :: "l"(addr), "f"(a), "f"(b), "f"(c), "f"(d) : "memory");
}

__global__ __launch_bounds__(256) void edge_kernel(
    const int* __restrict__ src_arr, const int* __restrict__ dst_arr,
    const float* __restrict__ alS, const float* __restrict__ alD,
    const __half* __restrict__ hf16,
    float* __restrict__ denom, float* __restrict__ acc)
{
    long gw = (long)blockIdx.x * (blockDim.x >> 5) + (threadIdx.x >> 5);
    if (gw >= E_EDGES) return;
    int lane = threadIdx.x & 31;
    int head = lane >> 3;

    int s = src_arr[gw];
    int d = dst_arr[gw];

    float v = alS[s * HEADS + head] + alD[d * HEADS + head];
    float e = v > 0.0f ? v : NEG_SLOPE * v;
    float w = __expf(e);

    if ((lane & 7) == 0) atomicAdd(&denom[d * HEADS + head], w);

    uint2 hv = ((const uint2*)hf16)[s * 32 + lane];
    float2 f0 = __half22float2(*(__half2*)&hv.x);
    float2 f1 = __half22float2(*(__half2*)&hv.y);
    red_add_v4(&acc[d * DDIM + lane * 4], w * f0.x, w * f0.y, w * f1.x, w * f1.y);
}

// ---------------- finalize GAT: g16 = fp16(relu(acc/denom + bg)) ----------------
__global__ void finalize_gat(
    const float* __restrict__ acc, const float* __restrict__ denom,
    const float* __restrict__ bg, __half* __restrict__ g16)
{
    int idx = blockIdx.x * blockDim.x + threadIdx.x;   // over N*32 float4s
    if (idx >= N_NODES * 32) return;
    int n = idx >> 5;
    int c4 = idx & 31;
    int head = c4 >> 3;
    float inv = 1.0f / (denom[n * HEADS + head] + 1e-16f);
    float4 a = ((const float4*)acc)[idx];
    float4 b = ((const float4*)bg)[c4];
    __half2 p0 = __floats2half2_rn(fmaxf(a.x * inv + b.x, 0.0f),
                                   fmaxf(a.y * inv + b.y, 0.0f));
    __half2 p1 = __floats2half2_rn(fmaxf(a.z * inv + b.z, 0.0f),
                                   fmaxf(a.w * inv + b.w, 0.0f));
    ((__half2*)g16)[idx * 2] = p0;
    ((__half2*)g16)[idx * 2 + 1] = p1;
}

// ---------------- GRU gates: fp16 gi/gh inputs ----------------
__global__ void gru_gates(
    const __half* __restrict__ gi, const __half* __restrict__ gh,
    float* __restrict__ h, __half* __restrict__ h16)
{
    int idx = blockIdx.x * blockDim.x + threadIdx.x;   // over N*32 float4 groups
    if (idx >= N_NODES * 32) return;
    int n = idx >> 5;
    long baseh = (long)n * D3 + (idx & 31) * 4;        // half index
    uint2 irv = *(const uint2*)&gi[baseh];
    uint2 hrv = *(const uint2*)&gh[baseh];
    uint2 izv = *(const uint2*)&gi[baseh + 128];
    uint2 hzv = *(const uint2*)&gh[baseh + 128];
    uint2 inv = *(const uint2*)&gi[baseh + 256];
    uint2 hnv = *(const uint2*)&gh[baseh + 256];
    float4 hv = ((const float4*)h)[idx];
    float ir[4], hr[4], iz[4], hz[4], in_[4], hn[4];
    {
        float2 a, b;
        a = __half22float2(*(__half2*)&irv.x); b = __half22float2(*(__half2*)&irv.y);
        ir[0]=a.x; ir[1]=a.y; ir[2]=b.x; ir[3]=b.y;
        a = __half22float2(*(__half2*)&hrv.x); b = __half22float2(*(__half2*)&hrv.y);
        hr[0]=a.x; hr[1]=a.y; hr[2]=b.x; hr[3]=b.y;
        a = __half22float2(*(__half2*)&izv.x); b = __half22float2(*(__half2*)&izv.y);
        iz[0]=a.x; iz[1]=a.y; iz[2]=b.x; iz[3]=b.y;
        a = __half22float2(*(__half2*)&hzv.x); b = __half22float2(*(__half2*)&hzv.y);
        hz[0]=a.x; hz[1]=a.y; hz[2]=b.x; hz[3]=b.y;
        a = __half22float2(*(__half2*)&inv.x); b = __half22float2(*(__half2*)&inv.y);
        in_[0]=a.x; in_[1]=a.y; in_[2]=b.x; in_[3]=b.y;
        a = __half22float2(*(__half2*)&hnv.x); b = __half22float2(*(__half2*)&hnv.y);
        hn[0]=a.x; hn[1]=a.y; hn[2]=b.x; hn[3]=b.y;
    }
    float4 ho;
#pragma unroll
    for (int q = 0; q < 4; q++) {
        float r = 1.0f / (1.0f + __expf(-(ir[q] + hr[q])));
        float z = 1.0f / (1.0f + __expf(-(iz[q] + hz[q])));
        float nn = tanh_fast(in_[q] + r * hn[q]);
        (&ho.x)[q] = (1.0f - z) * nn + z * (&hv.x)[q];
    }
    ((float4*)h)[idx] = ho;
    ((__half2*)h16)[idx * 2]     = __floats2half2_rn(ho.x, ho.y);
    ((__half2*)h16)[idx * 2 + 1] = __floats2half2_rn(ho.z, ho.w);
}

// ---------------- final linear ----------------
__global__ __launch_bounds__(256) void final_linear(
    const float* __restrict__ h, const float* __restrict__ Wl,
    const float* __restrict__ bl, float* __restrict__ out)
{
    int warp = (blockIdx.x * blockDim.x + threadIdx.x) >> 5;
    int lane = threadIdx.x & 31;
    if (warp >= N_NODES) return;
    float4 hv = ((const float4*)h)[warp * 32 + lane];
    float4 wv = ((const float4*)Wl)[lane];
    float s = hv.x * wv.x + hv.y * wv.y + hv.z * wv.z + hv.w * wv.w;
#pragma unroll
    for (int off = 16; off > 0; off >>= 1)
        s += __shfl_down_sync(0xffffffffu, s, off);
    if (lane == 0) out[warp] = s + bl[0];
}

// ---------------- launcher ----------------
extern "C" void kernel_launch(void* const* d_in, const int* in_sizes, int n_in,
                              void* d_out, int out_size)
{
    const float* x   = (const float*)d_in[0];
    const int*   ei  = (const int*)d_in[1];
    const float* Wg  = (const float*)d_in[2];
    const float* as  = (const float*)d_in[3];
    const float* ad  = (const float*)d_in[4];
    const float* bg  = (const float*)d_in[5];
    const float* Wih = (const float*)d_in[6];
    const float* Whh = (const float*)d_in[7];
    const float* bih = (const float*)d_in[8];
    const float* bhh = (const float*)d_in[9];
    const float* Wl  = (const float*)d_in[10];
    const float* bl  = (const float*)d_in[11];
    float* out = (float*)d_out;

    float *alS, *alD, *denom, *acc, *hstate;
    __half *Wg16, *Wih16, *Whh16, *hf16, *g16, *gi16, *gh16, *h16;
    cudaGetSymbolAddress((void**)&alS,    d_alS);
    cudaGetSymbolAddress((void**)&alD,    d_alD);
    cudaGetSymbolAddress((void**)&denom,  d_denom);
    cudaGetSymbolAddress((void**)&acc,    d_acc);
    cudaGetSymbolAddress((void**)&hstate, d_hstate);
    cudaGetSymbolAddress((void**)&Wg16,   d_Wg16);
    cudaGetSymbolAddress((void**)&Wih16,  d_Wih16);
    cudaGetSymbolAddress((void**)&Whh16,  d_Whh16);
    cudaGetSymbolAddress((void**)&hf16,   d_hf16);
    cudaGetSymbolAddress((void**)&g16,    d_g16);
    cudaGetSymbolAddress((void**)&gi16,   d_gi16);
    cudaGetSymbolAddress((void**)&gh16,   d_gh16);
    cudaGetSymbolAddress((void**)&h16,    d_h16);

    cudaFuncSetAttribute(gemm_att,
                         cudaFuncAttributeMaxDynamicSharedMemorySize, ATT_SMEM_BYTES);
    cudaFuncSetAttribute(gemm_f16_dual,
                         cudaFuncAttributeMaxDynamicSharedMemorySize, GEMM_SMEM_BYTES);

    const int GX = (N_NODES + 127) / 128;   // 391

    // prologue: zero state, convert weights to fp16
    zero_kernel<<<(ND + 255) / 256, 256>>>(hstate, h16, ND);
    conv_wg<<<(DDIM * F_IN + 255) / 256, 256>>>(Wg, Wg16);
    conv_w_nk<<<(D3 * DDIM + 255) / 256, 256>>>(Wih, Wih16, D3 * DDIM);
    conv_w_nk<<<(D3 * DDIM + 255) / 256, 256>>>(Whh, Whh16, D3 * DDIM);

    // ALL timesteps' GAT GEMM + attention logits in ONE launch (depends only on x)
    gemm_att<<<dim3(GX, T_STEPS), 256, ATT_SMEM_BYTES>>>(
        x, N_NODES, Wg16, hf16, as, ad, alS, alD, denom, acc);

    for (int t = 0; t < T_STEPS; t++) {
        __half* hf_t = hf16 + (long)t * ND;
        float* alS_t = alS + (long)t * NH;
        float* alD_t = alD + (long)t * NH;
        float* dn_t  = denom + (long)t * NH;
        float* acc_t = acc + (long)t * ND;

        // 1) edge pass (fp16 gather, fp32 RED accumulate)
        const int* src = ei + (long)t * 2 * E_EDGES;
        const int* dst = src + E_EDGES;
        edge_kernel<<<(E_EDGES * 32 + 255) / 256, 256>>>(src, dst, alS_t, alD_t, hf_t, dn_t, acc_t);

        // 2) g16 = fp16(relu(acc/denom + b_gat))
        finalize_gat<<<(N_NODES * 32 + 255) / 256, 256>>>(acc_t, dn_t, bg, g16);

        // 3) gi16 = g16 @ Wih^T + b_ih ; gh16 = h16 @ Whh^T + b_hh (fp16 out)
        gemm_f16_dual<<<dim3(GX, 6), 256, GEMM_SMEM_BYTES>>>(
            g16, h16, N_NODES, Wih16, Whh16, bih, bhh, gi16, gh16);

        // 4) GRU update (writes exact h + fp16 copy)
        gru_gates<<<(N_NODES * 32 + 255) / 256, 256>>>(gi16, gh16, hstate, h16);
    }

    final_linear<<<(N_NODES * 32 + 255) / 256, 256>>>(hstate, Wl, bl, out);
}

// round 13
// speedup vs baseline: 1.1131x; 1.0096x over previous
#include <cuda_runtime.h>
#include <cuda_fp16.h>
#include <cstdint>

// Problem constants (fixed shapes)
#define N_NODES 50000
#define T_STEPS 12
#define F_IN    128
#define HEADS   4
#define DDIM    128
#define E_EDGES 800000
#define NEG_SLOPE 0.2f
#define D3      384

#define ND (N_NODES * DDIM)
#define NH (N_NODES * HEADS)

// ---------------- scratch (device globals) ----------------
__device__ __half d_Wg16[DDIM * F_IN];     // [n][k]
__device__ __half d_Wih16[D3 * DDIM];      // [n][k] (native row-major)
__device__ __half d_Whh16[D3 * DDIM];
// per-timestep tensors (hoisted out of the recurrence)
__device__ __half d_hf16[T_STEPS][ND];     // fp16 h features (edge gather)
__device__ float  d_alS[T_STEPS][NH];
__device__ float  d_alD[T_STEPS][NH];
__device__ float  d_denom[T_STEPS][NH];
__device__ float  d_acc[T_STEPS][ND];
__device__ __half d_g16[T_STEPS][ND];      // relu'd GAT output (fp16)
__device__ __half d_gi16[T_STEPS][N_NODES * D3];  // input-gate preacts (fp16)
// recurrence scratch
__device__ __half d_gh16[N_NODES * D3];
__device__ float  d_hstate[ND];            // exact fp32 GRU state
__device__ __half d_h16[ND];               // fp16 copy (GEMM input)

#define ROWH 136                            // halves per smem row (pad)
#define TILEH (128 * ROWH)                  // halves per 128-row tile
#define GEMM_SMEM_BYTES (2 * TILEH * 2)
#define ATT_SMEM_BYTES  (2 * TILEH * 2 + 2 * 512 * 4)

__device__ __forceinline__ void mma16816(float* c, const uint32_t* a, const uint32_t* b) {
    asm volatile(
        "mma.sync.aligned.m16n8k16.row.col.f32.f16.f16.f32 "
        "{%0,%1,%2,%3}, {%4,%5,%6,%7}, {%8,%9}, {%0,%1,%2,%3};\n"
        : "+f"(c[0]), "+f"(c[1]), "+f"(c[2]), "+f"(c[3])
        : "r"(a[0]), "r"(a[1]), "r"(a[2]), "r"(a[3]), "r"(b[0]), "r"(b[1]));
}

__device__ __forceinline__ void cp_async16(uint32_t saddr, const void* gptr, int srcsize) {
    asm volatile("cp.async.cg.shared.global [%0], [%1], 16, %2;"
                 :: "r"(saddr), "l"(gptr), "r"(srcsize));
}

__device__ __forceinline__ float tanh_fast(float x) {
    float r;
    asm("tanh.approx.f32 %0, %1;" : "=f"(r) : "f"(x));
    return r;
}

// ---------------- utility kernels ----------------
__global__ void zero_kernel(float* p, __half* q, int n) {
    int i = blockIdx.x * blockDim.x + threadIdx.x;
    if (i < n) { p[i] = 0.0f; q[i] = __float2half(0.0f); }
}

__global__ void conv_w_nk(const float* __restrict__ W, __half* __restrict__ W16, int n) {
    int i = blockIdx.x * blockDim.x + threadIdx.x;
    if (i < n) W16[i] = __float2half_rn(W[i]);
}

// Wg [k][n] row-major -> Wg16 [n][k]
__global__ void conv_wg(const float* __restrict__ Wg, __half* __restrict__ Wg16) {
    int i = blockIdx.x * blockDim.x + threadIdx.x;
    if (i < DDIM * F_IN) {
        int n = i >> 7, k = i & 127;
        Wg16[i] = __float2half_rn(Wg[k * DDIM + n]);
    }
}

// ---------------- batched fp16 GEMM + fused attention epilogue ----------------
// grid (391, T_STEPS): blockIdx.y = timestep.
__global__ __launch_bounds__(256, 2) void gemm_att(
    const float* __restrict__ X, int M,
    const __half* __restrict__ Wt,
    __half* __restrict__ hf16_all,
    const float* __restrict__ a_src, const float* __restrict__ a_dst,
    float* __restrict__ alS_all, float* __restrict__ alD_all,
    float* __restrict__ denom_all, float* __restrict__ acc_all)
{
    extern __shared__ __half smh[];
    __half* As = smh;                 // [128][ROWH]
    __half* Ws = smh + TILEH;         // [128][ROWH]
    float* sS = (float*)(smh + 2 * TILEH);   // [512]
    float* sD = sS + 512;

    const int t = blockIdx.y;
    const float* A = X + (long)t * F_IN;
    const int lda = T_STEPS * F_IN;
    __half* hf16 = hf16_all + (long)t * ND;
    float* alS   = alS_all + (long)t * NH;
    float* alD   = alD_all + (long)t * NH;
    float* denom = denom_all + (long)t * NH;
    float* acc   = acc_all + (long)t * ND;

    const int tid  = threadIdx.x;
    const int lane = tid & 31;
    const int wid  = tid >> 5;
    const int wm   = (wid & 3) * 32;
    const int wn   = (wid >> 2) * 64;
    const int row0 = blockIdx.x * 128;
    const int lq   = lane >> 2;
    const int lr   = lane & 3;

    if (tid < 256) { sS[tid] = 0.f; sS[tid + 256] = 0.f;
                     sD[tid] = 0.f; sD[tid + 256] = 0.f; }

    const uint32_t sW = (uint32_t)__cvta_generic_to_shared(Ws);
    {
        int ra = tid >> 4, c16 = tid & 15;
#pragma unroll
        for (int i = 0; i < 8; i++) {
            int r = ra + i * 16;
            cp_async16(sW + (uint32_t)((r * ROWH + c16 * 8) * 2),
                       &Wt[(long)r * 128 + c16 * 8], 16);
        }
        asm volatile("cp.async.commit_group;");
    }
    {
        int rb = tid >> 5, c4 = tid & 31;
#pragma unroll
        for (int i = 0; i < 16; i++) {
            int r = rb + i * 8;
            int gr = row0 + r;
            float4 v = make_float4(0.f, 0.f, 0.f, 0.f);
            if (gr < M) v = *(const float4*)&A[(long)gr * lda + c4 * 4];
            __half2 h0 = __floats2half2_rn(v.x, v.y);
            __half2 h1 = __floats2half2_rn(v.z, v.w);
            __half2* dp = (__half2*)&As[r * ROWH + c4 * 4];
            dp[0] = h0; dp[1] = h1;
        }
    }
    asm volatile("cp.async.wait_group 0;");
    __syncthreads();

    float cacc[2][8][4];
#pragma unroll
    for (int mf = 0; mf < 2; mf++)
#pragma unroll
        for (int nf = 0; nf < 8; nf++)
#pragma unroll
            for (int q = 0; q < 4; q++) cacc[mf][nf][q] = 0.0f;

#pragma unroll
    for (int ks = 0; ks < 8; ks++) {
        const int kh = ks * 16;
        uint32_t af[2][4];
#pragma unroll
        for (int mf = 0; mf < 2; mf++) {
            int rw = wm + mf * 16 + lq;
            af[mf][0] = *(const uint32_t*)&As[rw * ROWH + kh + 2 * lr];
            af[mf][1] = *(const uint32_t*)&As[(rw + 8) * ROWH + kh + 2 * lr];
            af[mf][2] = *(const uint32_t*)&As[rw * ROWH + kh + 8 + 2 * lr];
            af[mf][3] = *(const uint32_t*)&As[(rw + 8) * ROWH + kh + 8 + 2 * lr];
        }
#pragma unroll
        for (int nf = 0; nf < 8; nf++) {
            int cc = wn + nf * 8 + lq;
            uint32_t bf[2];
            bf[0] = *(const uint32_t*)&Ws[cc * ROWH + kh + 2 * lr];
            bf[1] = *(const uint32_t*)&Ws[cc * ROWH + kh + 8 + 2 * lr];
#pragma unroll
            for (int mf = 0; mf < 2; mf++)
                mma16816(cacc[mf][nf], af[mf], bf);
        }
    }

    // ===== fused attention epilogue =====
    __syncthreads();
    {
        float aSv[8][2], aDv[8][2];
#pragma unroll
        for (int nf = 0; nf < 8; nf++) {
            int cc = wn + nf * 8 + lr * 2;
            aSv[nf][0] = a_src[cc];     aSv[nf][1] = a_src[cc + 1];
            aDv[nf][0] = a_dst[cc];     aDv[nf][1] = a_dst[cc + 1];
        }
#pragma unroll
        for (int mf = 0; mf < 2; mf++) {
#pragma unroll
            for (int half = 0; half < 2; half++) {
                int lrow = wm + mf * 16 + lq + half * 8;
                int h0 = wn >> 5;
                float pS0 = 0.f, pD0 = 0.f, pS1 = 0.f, pD1 = 0.f;
#pragma unroll
                for (int nf = 0; nf < 4; nf++) {
                    float v0 = cacc[mf][nf][half * 2], v1 = cacc[mf][nf][half * 2 + 1];
                    pS0 += v0 * aSv[nf][0] + v1 * aSv[nf][1];
                    pD0 += v0 * aDv[nf][0] + v1 * aDv[nf][1];
                }
#pragma unroll
                for (int nf = 4; nf < 8; nf++) {
                    float v0 = cacc[mf][nf][half * 2], v1 = cacc[mf][nf][half * 2 + 1];
                    pS1 += v0 * aSv[nf][0] + v1 * aSv[nf][1];
                    pD1 += v0 * aDv[nf][0] + v1 * aDv[nf][1];
                }
                atomicAdd(&sS[lrow * HEADS + h0], pS0);
                atomicAdd(&sD[lrow * HEADS + h0], pD0);
                atomicAdd(&sS[lrow * HEADS + h0 + 1], pS1);
                atomicAdd(&sD[lrow * HEADS + h0 + 1], pD1);
            }
        }
    }
    __syncthreads();
    for (int i = tid; i < 128 * HEADS; i += 256) {
        int lrow = i >> 2;
        int gr = row0 + lrow;
        if (gr < M) {
            float sg = sS[i], dg = sD[i];
            float v = sg + dg;
            float e = v > 0.0f ? v : NEG_SLOPE * v;
            float w = __expf(e);
            alS[(long)gr * HEADS + (i & 3)] = sg;
            alD[(long)gr * HEADS + (i & 3)] = dg;
            denom[(long)gr * HEADS + (i & 3)] = w;
            sD[i] = w;
        }
    }
    __syncthreads();
#pragma unroll
    for (int mf = 0; mf < 2; mf++) {
        int lrow = wm + mf * 16 + lq;
#pragma unroll
        for (int nf = 0; nf < 8; nf++) {
            int cc = wn + nf * 8 + lr * 2;
            int head = cc >> 5;
            int r_b = row0 + lrow;
            if (r_b < M) {
                float w = sD[lrow * HEADS + head];
                float2 o = make_float2(cacc[mf][nf][0], cacc[mf][nf][1]);
                *(__half2*)&hf16[(long)r_b * DDIM + cc] = __floats2half2_rn(o.x, o.y);
                *(float2*)&acc[(long)r_b * DDIM + cc] = make_float2(o.x * w, o.y * w);
            }
            if (r_b + 8 < M) {
                float w = sD[(lrow + 8) * HEADS + head];
                float2 o = make_float2(cacc[mf][nf][2], cacc[mf][nf][3]);
                *(__half2*)&hf16[(long)(r_b + 8) * DDIM + cc] = __floats2half2_rn(o.x, o.y);
                *(float2*)&acc[(long)(r_b + 8) * DDIM + cc] = make_float2(o.x * w, o.y * w);
            }
        }
    }
}

// ---------------- generic fp16 GEMM, batched over z ----------------
// grid (GX, 3, NB): C[z] (+c0 chunk) = A[z] @ W^T + bias. Astr/Cstr = z strides.
__global__ __launch_bounds__(256, 2) void gemm_f16_b(
    const __half* __restrict__ Abase, long Astr, int M,
    const __half* __restrict__ Wt,
    const float* __restrict__ bias,
    __half* __restrict__ Cbase, long Cstr)
{
    extern __shared__ __half smh[];
    __half* As = smh;
    __half* Ws = smh + TILEH;

    const __half* A = Abase + (long)blockIdx.z * Astr;
    __half* C = Cbase + (long)blockIdx.z * Cstr;
    const int c0 = blockIdx.y * 128;

    const int tid  = threadIdx.x;
    const int lane = tid & 31;
    const int wid  = tid >> 5;
    const int wm   = (wid & 3) * 32;
    const int wn   = (wid >> 2) * 64;
    const int row0 = blockIdx.x * 128;
    const int lq   = lane >> 2;
    const int lr   = lane & 3;

    const uint32_t sA = (uint32_t)__cvta_generic_to_shared(As);
    const uint32_t sW = (uint32_t)__cvta_generic_to_shared(Ws);
    {
        int ra = tid >> 4, c16 = tid & 15;
#pragma unroll
        for (int i = 0; i < 8; i++) {
            int r = ra + i * 16;
            int gr = row0 + r;
            const __half* gp = &A[(long)(gr < M ? gr : 0) * 128 + c16 * 8];
            cp_async16(sA + (uint32_t)((r * ROWH + c16 * 8) * 2), gp, gr < M ? 16 : 0);
        }
#pragma unroll
        for (int i = 0; i < 8; i++) {
            int r = ra + i * 16;
            cp_async16(sW + (uint32_t)((r * ROWH + c16 * 8) * 2),
                       &Wt[(long)(c0 + r) * 128 + c16 * 8], 16);
        }
        asm volatile("cp.async.commit_group;");
        asm volatile("cp.async.wait_group 0;");
    }
    __syncthreads();

    float cacc[2][8][4];
#pragma unroll
    for (int mf = 0; mf < 2; mf++)
#pragma unroll
        for (int nf = 0; nf < 8; nf++)
#pragma unroll
            for (int q = 0; q < 4; q++) cacc[mf][nf][q] = 0.0f;

#pragma unroll
    for (int ks = 0; ks < 8; ks++) {
        const int kh = ks * 16;
        uint32_t af[2][4];
#pragma unroll
        for (int mf = 0; mf < 2; mf++) {
            int rw = wm + mf * 16 + lq;
            af[mf][0] = *(const uint32_t*)&As[rw * ROWH + kh + 2 * lr];
            af[mf][1] = *(const uint32_t*)&As[(rw + 8) * ROWH + kh + 2 * lr];
            af[mf][2] = *(const uint32_t*)&As[rw * ROWH + kh + 8 + 2 * lr];
            af[mf][3] = *(const uint32_t*)&As[(rw + 8) * ROWH + kh + 8 + 2 * lr];
        }
#pragma unroll
        for (int nf = 0; nf < 8; nf++) {
            int cc = wn + nf * 8 + lq;
            uint32_t bf[2];
            bf[0] = *(const uint32_t*)&Ws[cc * ROWH + kh + 2 * lr];
            bf[1] = *(const uint32_t*)&Ws[cc * ROWH + kh + 8 + 2 * lr];
#pragma unroll
            for (int mf = 0; mf < 2; mf++)
                mma16816(cacc[mf][nf], af[mf], bf);
        }
    }

#pragma unroll
    for (int mf = 0; mf < 2; mf++) {
        int r_b = row0 + wm + mf * 16 + lq;
#pragma unroll
        for (int nf = 0; nf < 8; nf++) {
            int cc = c0 + wn + nf * 8 + lr * 2;
            float b0 = bias[cc];
            float b1 = bias[cc + 1];
            if (r_b < M)
                *(__half2*)&C[(long)r_b * D3 + cc] =
                    __floats2half2_rn(cacc[mf][nf][0] + b0, cacc[mf][nf][1] + b1);
            if (r_b + 8 < M)
                *(__half2*)&C[(long)(r_b + 8) * D3 + cc] =
                    __floats2half2_rn(cacc[mf][nf][2] + b0, cacc[mf][nf][3] + b1);
        }
    }
}

// ---------------- batched edge pass: grid.y = timestep ----------------
__device__ __forceinline__ void red_add_v4(float* addr, float a, float b, float c, float d) {
    asm volatile("red.global.add.v4.f32 [%0], {%1,%2,%3,%4};"
                 :: "l"(addr), "f"(a), "f"(b), "f"(c), "f"(d) : "memory");
}

__global__ __launch_bounds__(256) void edge_kernel(
    const int* __restrict__ ei,
    const float* __restrict__ alS_all, const float* __restrict__ alD_all,
    const __half* __restrict__ hf16_all,
    float* __restrict__ denom_all, float* __restrict__ acc_all)
{
    const int t = blockIdx.y;
    const int* src_arr = ei + (long)t * 2 * E_EDGES;
    const int* dst_arr = src_arr + E_EDGES;
    const float* alS = alS_all + (long)t * NH;
    const float* alD = alD_all + (long)t * NH;
    const __half* hf16 = hf16_all + (long)t * ND;
    float* denom = denom_all + (long)t * NH;
    float* acc   = acc_all + (long)t * ND;

    long gw = (long)blockIdx.x * (blockDim.x >> 5) + (threadIdx.x >> 5);
    if (gw >= E_EDGES) return;
    int lane = threadIdx.x & 31;
    int head = lane >> 3;

    int s = src_arr[gw];
    int d = dst_arr[gw];

    float v = alS[s * HEADS + head] + alD[d * HEADS + head];
    float e = v > 0.0f ? v : NEG_SLOPE * v;
    float w = __expf(e);

    if ((lane & 7) == 0) atomicAdd(&denom[d * HEADS + head], w);

    uint2 hv = ((const uint2*)hf16)[s * 32 + lane];
    float2 f0 = __half22float2(*(__half2*)&hv.x);
    float2 f1 = __half22float2(*(__half2*)&hv.y);
    red_add_v4(&acc[d * DDIM + lane * 4], w * f0.x, w * f0.y, w * f1.x, w * f1.y);
}

// ---------------- batched finalize: grid.y = timestep ----------------
__global__ void finalize_gat(
    const float* __restrict__ acc_all, const float* __restrict__ denom_all,
    const float* __restrict__ bg, __half* __restrict__ g16_all)
{
    const int t = blockIdx.y;
    const float* acc = acc_all + (long)t * ND;
    const float* denom = denom_all + (long)t * NH;
    __half* g16 = g16_all + (long)t * ND;

    int idx = blockIdx.x * blockDim.x + threadIdx.x;   // over N*32 float4s
    if (idx >= N_NODES * 32) return;
    int n = idx >> 5;
    int c4 = idx & 31;
    int head = c4 >> 3;
    float inv = 1.0f / (denom[n * HEADS + head] + 1e-16f);
    float4 a = ((const float4*)acc)[idx];
    float4 b = ((const float4*)bg)[c4];
    __half2 p0 = __floats2half2_rn(fmaxf(a.x * inv + b.x, 0.0f),
                                   fmaxf(a.y * inv + b.y, 0.0f));
    __half2 p1 = __floats2half2_rn(fmaxf(a.z * inv + b.z, 0.0f),
                                   fmaxf(a.w * inv + b.w, 0.0f));
    ((__half2*)g16)[idx * 2] = p0;
    ((__half2*)g16)[idx * 2 + 1] = p1;
}

// ---------------- GRU gates: fp16 gi/gh inputs ----------------
__global__ void gru_gates(
    const __half* __restrict__ gi, const __half* __restrict__ gh,
    float* __restrict__ h, __half* __restrict__ h16)
{
    int idx = blockIdx.x * blockDim.x + threadIdx.x;   // over N*32 float4 groups
    if (idx >= N_NODES * 32) return;
    int n = idx >> 5;
    long baseh = (long)n * D3 + (idx & 31) * 4;        // half index
    uint2 irv = *(const uint2*)&gi[baseh];
    uint2 hrv = *(const uint2*)&gh[baseh];
    uint2 izv = *(const uint2*)&gi[baseh + 128];
    uint2 hzv = *(const uint2*)&gh[baseh + 128];
    uint2 inv = *(const uint2*)&gi[baseh + 256];
    uint2 hnv = *(const uint2*)&gh[baseh + 256];
    float4 hv = ((const float4*)h)[idx];
    float ir[4], hr[4], iz[4], hz[4], in_[4], hn[4];
    {
        float2 a, b;
        a = __half22float2(*(__half2*)&irv.x); b = __half22float2(*(__half2*)&irv.y);
        ir[0]=a.x; ir[1]=a.y; ir[2]=b.x; ir[3]=b.y;
        a = __half22float2(*(__half2*)&hrv.x); b = __half22float2(*(__half2*)&hrv.y);
        hr[0]=a.x; hr[1]=a.y; hr[2]=b.x; hr[3]=b.y;
        a = __half22float2(*(__half2*)&izv.x); b = __half22float2(*(__half2*)&izv.y);
        iz[0]=a.x; iz[1]=a.y; iz[2]=b.x; iz[3]=b.y;
        a = __half22float2(*(__half2*)&hzv.x); b = __half22float2(*(__half2*)&hzv.y);
        hz[0]=a.x; hz[1]=a.y; hz[2]=b.x; hz[3]=b.y;
        a = __half22float2(*(__half2*)&inv.x); b = __half22float2(*(__half2*)&inv.y);
        in_[0]=a.x; in_[1]=a.y; in_[2]=b.x; in_[3]=b.y;
        a = __half22float2(*(__half2*)&hnv.x); b = __half22float2(*(__half2*)&hnv.y);
        hn[0]=a.x; hn[1]=a.y; hn[2]=b.x; hn[3]=b.y;
    }
    float4 ho;
#pragma unroll
    for (int q = 0; q < 4; q++) {
        float r = 1.0f / (1.0f + __expf(-(ir[q] + hr[q])));
        float z = 1.0f / (1.0f + __expf(-(iz[q] + hz[q])));
        float nn = tanh_fast(in_[q] + r * hn[q]);
        (&ho.x)[q] = (1.0f - z) * nn + z * (&hv.x)[q];
    }
    ((float4*)h)[idx] = ho;
    ((__half2*)h16)[idx * 2]     = __floats2half2_rn(ho.x, ho.y);
    ((__half2*)h16)[idx * 2 + 1] = __floats2half2_rn(ho.z, ho.w);
}

// ---------------- final linear ----------------
__global__ __launch_bounds__(256) void final_linear(
    const float* __restrict__ h, const float* __restrict__ Wl,
    const float* __restrict__ bl, float* __restrict__ out)
{
    int warp = (blockIdx.x * blockDim.x + threadIdx.x) >> 5;
    int lane = threadIdx.x & 31;
    if (warp >= N_NODES) return;
    float4 hv = ((const float4*)h)[warp * 32 + lane];
    float4 wv = ((const float4*)Wl)[lane];
    float s = hv.x * wv.x + hv.y * wv.y + hv.z * wv.z + hv.w * wv.w;
#pragma unroll
    for (int off = 16; off > 0; off >>= 1)
        s += __shfl_down_sync(0xffffffffu, s, off);
    if (lane == 0) out[warp] = s + bl[0];
}

// ---------------- launcher ----------------
extern "C" void kernel_launch(void* const* d_in, const int* in_sizes, int n_in,
                              void* d_out, int out_size)
{
    const float* x   = (const float*)d_in[0];
    const int*   ei  = (const int*)d_in[1];
    const float* Wg  = (const float*)d_in[2];
    const float* as  = (const float*)d_in[3];
    const float* ad  = (const float*)d_in[4];
    const float* bg  = (const float*)d_in[5];
    const float* Wih = (const float*)d_in[6];
    const float* Whh = (const float*)d_in[7];
    const float* bih = (const float*)d_in[8];
    const float* bhh = (const float*)d_in[9];
    const float* Wl  = (const float*)d_in[10];
    const float* bl  = (const float*)d_in[11];
    float* out = (float*)d_out;

    float *alS, *alD, *denom, *acc, *hstate;
    __half *Wg16, *Wih16, *Whh16, *hf16, *g16, *gi16, *gh16, *h16;
    cudaGetSymbolAddress((void**)&alS,    d_alS);
    cudaGetSymbolAddress((void**)&alD,    d_alD);
    cudaGetSymbolAddress((void**)&denom,  d_denom);
    cudaGetSymbolAddress((void**)&acc,    d_acc);
    cudaGetSymbolAddress((void**)&hstate, d_hstate);
    cudaGetSymbolAddress((void**)&Wg16,   d_Wg16);
    cudaGetSymbolAddress((void**)&Wih16,  d_Wih16);
    cudaGetSymbolAddress((void**)&Whh16,  d_Whh16);
    cudaGetSymbolAddress((void**)&hf16,   d_hf16);
    cudaGetSymbolAddress((void**)&g16,    d_g16);
    cudaGetSymbolAddress((void**)&gi16,   d_gi16);
    cudaGetSymbolAddress((void**)&gh16,   d_gh16);
    cudaGetSymbolAddress((void**)&h16,    d_h16);

    cudaFuncSetAttribute(gemm_att,
                         cudaFuncAttributeMaxDynamicSharedMemorySize, ATT_SMEM_BYTES);
    cudaFuncSetAttribute(gemm_f16_b,
                         cudaFuncAttributeMaxDynamicSharedMemorySize, GEMM_SMEM_BYTES);

    const int GX = (N_NODES + 127) / 128;   // 391

    // prologue: zero state, convert weights to fp16
    zero_kernel<<<(ND + 255) / 256, 256>>>(hstate, h16, ND);
    conv_wg<<<(DDIM * F_IN + 255) / 256, 256>>>(Wg, Wg16);
    conv_w_nk<<<(D3 * DDIM + 255) / 256, 256>>>(Wih, Wih16, D3 * DDIM);
    conv_w_nk<<<(D3 * DDIM + 255) / 256, 256>>>(Whh, Whh16, D3 * DDIM);

    // ===== hoisted, batched non-recurrent pipeline =====
    // 1) all GAT GEMMs + attention logits
    gemm_att<<<dim3(GX, T_STEPS), 256, ATT_SMEM_BYTES>>>(
        x, N_NODES, Wg16, hf16, as, ad, alS, alD, denom, acc);
    // 2) all edge passes
    edge_kernel<<<dim3((E_EDGES * 32 + 255) / 256, T_STEPS), 256>>>(
        ei, alS, alD, hf16, denom, acc);
    // 3) all finalizes -> g16[t]
    finalize_gat<<<dim3((N_NODES * 32 + 255) / 256, T_STEPS), 256>>>(acc, denom, bg, g16);
    // 4) all input-gate GEMMs -> gi16[t]
    gemm_f16_b<<<dim3(GX, 3, T_STEPS), 256, GEMM_SMEM_BYTES>>>(
        g16, (long)ND, N_NODES, Wih16, bih, gi16, (long)N_NODES * D3);

    // ===== recurrence: only gh + gates =====
    for (int t = 0; t < T_STEPS; t++) {
        gemm_f16_b<<<dim3(GX, 3, 1), 256, GEMM_SMEM_BYTES>>>(
            h16, 0L, N_NODES, Whh16, bhh, gh16, 0L);
        gru_gates<<<(N_NODES * 32 + 255) / 256, 256>>>(
            gi16 + (long)t * N_NODES * D3, gh16, hstate, h16);
    }

    final_linear<<<(N_NODES * 32 + 255) / 256, 256>>>(hstate, Wl, bl, out);
}